// round 14
// baseline (speedup 1.0000x reference)
#include <cuda_runtime.h>
#include <cstdint>
#include <math.h>

// Problem dimensions
#define BB 256
#define TT 64
#define EE 1024
#define AA 6
#define DD 256
#define SS 32
#define CC 32
#define HH 256
#define SDIM 1024
#define OUTW 4352   // 4*SD + D per (b,t)

#define NGUM (2 * TT * BB * SS * CC)   // 4,194,304 elements (16 MB)

// Background items per step: 256 epart K-quarter tiles + 16 gumbel eighths.
// Hosted: items [0,136) in k_gates, items [136,272) in k_out.
#define NQITEMS   272
#define GATES_BG  136
#define OUT_BG    (NQITEMS - GATES_BG)   // 136
#define GATES_GEMM 96
#define OUT_GEMM   128

// ---------------- device scratch (no allocation allowed) ----------------
__device__ float g_gumbel[NGUM];
__device__ float g_deter[BB * DD];
__device__ float g_x[BB * HH];                      // GRU input x(t)
__device__ float g_gi[BB * 768];
__device__ float g_gh[BB * 768];
__device__ float g_dpart[BB * SDIM];                // deter part of post logits
// epart K-quarters, T-MAJOR: g_epQ[c][(t*BB+b)*SDIM + n]
__device__ float g_epQ[4][(long)TT * BB * SDIM];

// ---------------- shared workspace --------------------------------------
struct GemmSmem {
    float As[2][16][64 + 4];
    float Bs[2][16][64];
};

// ---------------- double-buffered fp32 tiled GEMM core ------------------
// C[m,n] = sum_{k in [k0,k0+kcnt)} A(m,k)*B[k,n_off+n] (+bias).
// Pure ascending-K per-element accumulation (bit-identical across tilings).
template<class AL>
__device__ __forceinline__ void gemm_db64(
    GemmSmem& ws, AL aload, const float* __restrict__ Bm, int ldb,
    int m_off, int n_off, int k0, int kcnt,
    float* __restrict__ C, long ldc, const float* __restrict__ bias)
{
    constexpr int BM = 64, BN = 64, BK = 16, NTHR = 256, TM = 4, TN = 4;
    const int tid = threadIdx.x;
    const int tx = tid % (BN / TN);
    const int ty = tid / (BN / TN);
    constexpr int ALD = BM * BK / NTHR;   // 4
    constexpr int BLD = BN * BK / NTHR;   // 4
    const int amk = tid % BK;
    const int am0 = tid / BK;
    const int bn  = tid % BN;
    const int bk0 = tid / BN;

    float rA[ALD], rB[BLD];
    float acc[TM][TN];
#pragma unroll
    for (int i = 0; i < TM; i++)
#pragma unroll
        for (int j = 0; j < TN; j++) acc[i][j] = 0.f;

    const int NT = kcnt / BK;

#pragma unroll
    for (int j = 0; j < ALD; j++)
        rA[j] = aload(m_off + am0 + j * (NTHR / BK), k0 + amk);
#pragma unroll
    for (int j = 0; j < BLD; j++)
        rB[j] = Bm[(long)(k0 + bk0 + j * (NTHR / BN)) * ldb + n_off + bn];
#pragma unroll
    for (int j = 0; j < ALD; j++) ws.As[0][amk][am0 + j * (NTHR / BK)] = rA[j];
#pragma unroll
    for (int j = 0; j < BLD; j++) ws.Bs[0][bk0 + j * (NTHR / BN)][bn] = rB[j];
    __syncthreads();

    for (int kt = 0; kt < NT; kt++) {
        int cur = kt & 1;
        if (kt + 1 < NT) {
            int kb = k0 + (kt + 1) * BK;
#pragma unroll
            for (int j = 0; j < ALD; j++)
                rA[j] = aload(m_off + am0 + j * (NTHR / BK), kb + amk);
#pragma unroll
            for (int j = 0; j < BLD; j++)
                rB[j] = Bm[(long)(kb + bk0 + j * (NTHR / BN)) * ldb + n_off + bn];
        }
#pragma unroll
        for (int kk = 0; kk < BK; kk++) {
            float4 av = *reinterpret_cast<const float4*>(&ws.As[cur][kk][ty * TM]);
            float4 bv = *reinterpret_cast<const float4*>(&ws.Bs[cur][kk][tx * TN]);
            float am[4] = {av.x, av.y, av.z, av.w};
            float bn_[4] = {bv.x, bv.y, bv.z, bv.w};
#pragma unroll
            for (int i = 0; i < TM; i++)
#pragma unroll
                for (int j = 0; j < TN; j++) acc[i][j] += am[i] * bn_[j];
        }
        if (kt + 1 < NT) {
            int nb = cur ^ 1;
#pragma unroll
            for (int j = 0; j < ALD; j++) ws.As[nb][amk][am0 + j * (NTHR / BK)] = rA[j];
#pragma unroll
            for (int j = 0; j < BLD; j++) ws.Bs[nb][bk0 + j * (NTHR / BN)][bn] = rB[j];
            __syncthreads();
        }
    }
#pragma unroll
    for (int i = 0; i < TM; i++) {
        int m = m_off + ty * TM + i;
#pragma unroll
        for (int j = 0; j < TN; j++) {
            int n = n_off + tx * TN + j;
            float v = acc[i][j];
            if (bias) v += bias[n];
            C[(long)m * ldc + n] = v;
        }
    }
}

// ---------------- A-loaders ----------------------------------------------
struct GiL {
    __device__ float operator()(int m, int k) const { return g_x[m * HH + k]; }
};
struct GhL {
    const float* isf; int t;
    __device__ float operator()(int m, int k) const {
        return g_deter[m * DD + k] * (1.0f - isf[m * TT + t]);
    }
};
struct DetL {
    __device__ float operator()(int m, int k) const { return g_deter[m * DD + k]; }
};
struct EpartL {
    const float* E;
    __device__ float operator()(int rho, int k) const {
        int t = rho >> 8, b = rho & 255;
        return E[((long)b * TT + t) * EE + k];
    }
};

// ---------------- JAX threefry2x32 gumbel (partitionable) ----------------
__device__ __forceinline__ uint32_t rotl32(uint32_t v, int r) {
    return (v << r) | (v >> (32 - r));
}
__device__ __forceinline__ float bits_to_gumbel(uint32_t b) {
    float u = __uint_as_float((b >> 9) | 0x3f800000u) - 1.0f;
    const float tinyv = 1.17549435e-38f;
    u = fmaxf(u, tinyv);
    double inner = -log((double)u);
    float innerf = (float)inner;
    double outer = -log((double)innerf);
    return (float)outer;
}
__device__ __forceinline__ float gumbel_elem(uint32_t gidx) {
    uint32_t x0 = 0u, x1 = gidx;
    const uint32_t ks0 = 0u, ks1 = 42u, ks2 = 0x1BD11BDAu ^ 0u ^ 42u;
    x0 += ks0; x1 += ks1;
#define TF_R4(a, b, c, d)                                   \
    x0 += x1; x1 = rotl32(x1, a); x1 ^= x0;                 \
    x0 += x1; x1 = rotl32(x1, b); x1 ^= x0;                 \
    x0 += x1; x1 = rotl32(x1, c); x1 ^= x0;                 \
    x0 += x1; x1 = rotl32(x1, d); x1 ^= x0;
    TF_R4(13, 15, 26, 6);  x0 += ks1; x1 += ks2 + 1u;
    TF_R4(17, 29, 16, 24); x0 += ks2; x1 += ks0 + 2u;
    TF_R4(13, 15, 26, 6);  x0 += ks0; x1 += ks1 + 3u;
    TF_R4(17, 29, 16, 24); x0 += ks1; x1 += ks2 + 4u;
    TF_R4(13, 15, 26, 6);  x0 += ks2; x1 += ks0 + 5u;
#undef TF_R4
    return bits_to_gumbel(x0 ^ x1);
}

// ---------------- precise transcendentals --------------------------------
__device__ __forceinline__ float sigm_precise(float x) {
    return (float)(1.0 / (1.0 + exp((double)(-x))));
}
__device__ __forceinline__ float tanh_precise(float x) {
    return (float)tanh((double)x);
}

// ---------------- background item executor (R12-validated numerics) ------
// Item i for step t1: i<256 -> epart K-quarter tile; else gumbel eighth.
__device__ __forceinline__ void run_bg_item(GemmSmem& ws, int t1, int i,
                                            const float* embed, const float* Woo) {
    if (i < 256) {
        int c = i & 3;            // k-quarter -> buffer c
        int tau = i >> 2;         // tile 0..63: rows (tau&3)*64, cols (tau>>2)*64
        gemm_db64(ws, EpartL{embed}, Woo + (long)DD * SDIM, SDIM,
                  t1 * BB + (tau & 3) * 64, (tau >> 2) * 64,
                  c * 256, 256, g_epQ[c], SDIM, nullptr);
    } else {
        int r = i - 256;          // 0..15
        int draw = r >> 3, eighth = r & 7;
        unsigned base = (unsigned)(draw * TT + t1) * 262144u
                      + (unsigned)eighth * 32768u;
        unsigned tid = threadIdx.x;
#pragma unroll 4
        for (int j = 0; j < 128; j++) {
            unsigned gidx = base + (unsigned)j * 256u + tid;
            g_gumbel[gidx] = gumbel_elem(gidx);
        }
    }
}

// ---------------- init: deter=0 + x(0) -----------------------------------
__global__ void k_init(const float* __restrict__ action, const float* __restrict__ W1,
                       const float* __restrict__ b1) {
    int i = blockIdx.x * blockDim.x + threadIdx.x;   // grid 256x256
    g_deter[i] = 0.f;
    if (i < BB * HH) {
        int b = i >> 8, col = i & 255;
        float c3 = 0.f;
#pragma unroll
        for (int a = 0; a < AA; a++)
            c3 = fmaf(action[(long)b * TT * AA + a], W1[(SDIM + a) * HH + col], c3);
        g_x[b * HH + col] = b1[col] + c3;
    }
}

// ---------------- prologue for t=0 (grid = NQITEMS, single wave) ---------
__global__ void __launch_bounds__(256)
k_pre(const float* __restrict__ embed, const float* __restrict__ Woo) {
    __shared__ GemmSmem ws;
    run_bg_item(ws, 0, blockIdx.x, embed, Woo);
}

// ---------------- gates GEMMs (+ hosted bg items for t+1) ----------------
__global__ void __launch_bounds__(256)
k_gates(const float* __restrict__ embed,
        const float* __restrict__ Wih, const float* __restrict__ bih,
        const float* __restrict__ Whh, const float* __restrict__ bhh,
        const float* __restrict__ Woo,
        const float* __restrict__ isf, int t) {
    __shared__ GemmSmem ws;
    const int bid = blockIdx.x;
    if (bid >= GATES_GEMM) {
        if (t + 1 < TT) run_bg_item(ws, t + 1, bid - GATES_GEMM, embed, Woo);
        return;
    }
    int bz = bid / 48, rem = bid % 48, by = rem / 12, bx = rem % 12;
    if (bz == 0)
        gemm_db64(ws, GiL{}, Wih, 768, by * 64, bx * 64, 0, DD, g_gi, 768, bih);
    else
        gemm_db64(ws, GhL{isf, t}, Whh, 768, by * 64, bx * 64, 0, DD, g_gh, 768, bhh);
}

// ---------------- GRU (R7 verbatim) --------------------------------------
__global__ void k_gru(const float* __restrict__ isf, float* __restrict__ out, int t) {
    int i = blockIdx.x * blockDim.x + threadIdx.x;
    int b = i >> 8, d = i & 255;
    float ir = g_gi[b * 768 + d], iz = g_gi[b * 768 + 256 + d], in_ = g_gi[b * 768 + 512 + d];
    float hr = g_gh[b * 768 + d], hz = g_gh[b * 768 + 256 + d], hn = g_gh[b * 768 + 512 + d];
    float r = sigm_precise(ir + hr);
    float z = sigm_precise(iz + hz);
    float n = tanh_precise(in_ + r * hn);
    float h = g_deter[i] * (1.0f - isf[b * TT + t]);
    float nd = (1.0f - z) * n + z * h;
    g_deter[i] = nd;
    out[((long)b * TT + t) * OUTW + 2048 + d] = nd;
}

// ---------------- out GEMMs (+ hosted bg items for t+1) ------------------
__global__ void __launch_bounds__(256)
k_out(const float* __restrict__ embed,
      const float* __restrict__ Wio, const float* __restrict__ bio,
      const float* __restrict__ Woo, float* __restrict__ out, int t) {
    __shared__ GemmSmem ws;
    const int bid = blockIdx.x;
    if (bid >= OUT_GEMM) {
        if (t + 1 < TT) run_bg_item(ws, t + 1, GATES_BG + (bid - OUT_GEMM), embed, Woo);
        return;
    }
    int bz = bid / 64, rem = bid % 64, by = rem / 16, bx = rem % 16;
    if (bz == 0)
        gemm_db64(ws, DetL{}, Wio, SDIM, by * 64, bx * 64, 0, DD,
                  out + (long)t * OUTW + 2304, (long)TT * OUTW, bio);
    else
        gemm_db64(ws, DetL{}, Woo, SDIM, by * 64, bx * 64, 0, DD,
                  g_dpart, SDIM, nullptr);
}

// ---------------- sampling + x feedback (R7 structure, R12 epart sum) ----
__global__ void k_sample(const float* __restrict__ isf, const float* __restrict__ action,
                         const float* __restrict__ W1, const float* __restrict__ b1,
                         const float* __restrict__ boo, float* __restrict__ out, int t) {
    int b = blockIdx.x;
    int draw = blockIdx.y;
    int tid = threadIdx.x, lane = tid & 31, w = tid >> 5;
    __shared__ int sidx[SS];
    long obase = ((long)b * TT + t) * OUTW;

#pragma unroll
    for (int q = 0; q < 4; q++) {
        int g = w * 4 + q;
        int col = g * 32 + lane;
        float lv;
        if (draw == 0) {
            lv = out[obase + 2304 + col];
        } else {
            long ei = ((long)t * BB + b) * SDIM + col;
            float ep = ((g_epQ[0][ei] + g_epQ[1][ei]) + g_epQ[2][ei]) + g_epQ[3][ei];
            lv = (g_dpart[b * SDIM + col] + ep) + boo[col];
            out[obase + col] = lv;
        }
        float gum = g_gumbel[(((long)draw * TT + t) * BB + b) * SDIM + col];
        float v = lv + gum;
        int idx = lane;
#pragma unroll
        for (int off = 16; off > 0; off >>= 1) {
            float v2 = __shfl_xor_sync(0xffffffffu, v, off);
            int i2 = __shfl_xor_sync(0xffffffffu, idx, off);
            if (v2 > v || (v2 == v && i2 < idx)) { v = v2; idx = i2; }
        }
        float oh = (lane == idx) ? 1.0f : 0.0f;
        out[obase + (draw ? 1024 : 3328) + col] = oh;
        if (draw && lane == 0) sidx[g] = idx;
    }

    if (draw == 1 && t + 1 < TT) {
        __syncthreads();
        int col = tid;
        float mask = 1.0f - isf[b * TT + (t + 1)];
        float c0 = 0.f, c1 = 0.f, c2 = 0.f, c3 = 0.f;
        int i8 = sidx[8], i25 = sidx[25];
#pragma unroll
        for (int s2 = 0; s2 < 8; s2++)
            c0 = fmaf(mask, W1[(s2 * 32 + sidx[s2]) * HH + col], c0);
        {
            float wv = W1[(8 * 32 + i8) * HH + col];
            if (i8 < 16) c0 = fmaf(mask, wv, c0); else c1 = fmaf(mask, wv, c1);
        }
#pragma unroll
        for (int s2 = 9; s2 < 17; s2++)
            c1 = fmaf(mask, W1[(s2 * 32 + sidx[s2]) * HH + col], c1);
#pragma unroll
        for (int s2 = 17; s2 < 25; s2++)
            c2 = fmaf(mask, W1[(s2 * 32 + sidx[s2]) * HH + col], c2);
        {
            float wv = W1[(25 * 32 + i25) * HH + col];
            if (i25 < 16) c2 = fmaf(mask, wv, c2); else c3 = fmaf(mask, wv, c3);
        }
#pragma unroll
        for (int s2 = 26; s2 < 32; s2++)
            c3 = fmaf(mask, W1[(s2 * 32 + sidx[s2]) * HH + col], c3);
#pragma unroll
        for (int a = 0; a < AA; a++)
            c3 = fmaf(action[((long)b * TT + (t + 1)) * AA + a],
                      W1[(SDIM + a) * HH + col], c3);
        g_x[b * HH + col] = (((c0 + b1[col]) + c1) + c2) + c3;
    }
}

// ---------------- launch ----------------
extern "C" void kernel_launch(void* const* d_in, const int* in_sizes, int n_in,
                              void* d_out, int out_size) {
    (void)in_sizes; (void)n_in; (void)out_size;
    const float* embed     = (const float*)d_in[0];
    const float* action    = (const float*)d_in[1];
    const float* isf       = (const float*)d_in[2];
    const float* W_img_in  = (const float*)d_in[3];
    const float* b_img_in  = (const float*)d_in[4];
    const float* W_ih      = (const float*)d_in[5];
    const float* b_ih      = (const float*)d_in[6];
    const float* W_hh      = (const float*)d_in[7];
    const float* b_hh      = (const float*)d_in[8];
    const float* W_img_out = (const float*)d_in[9];
    const float* b_img_out = (const float*)d_in[10];
    const float* W_obs_out = (const float*)d_in[11];
    const float* b_obs_out = (const float*)d_in[12];
    float* out = (float*)d_out;

    k_init<<<256, 256>>>(action, W_img_in, b_img_in);
    k_pre<<<NQITEMS, 256>>>(embed, W_obs_out);
    for (int t = 0; t < TT; t++) {
        k_gates<<<GATES_GEMM + GATES_BG, 256>>>(embed, W_ih, b_ih, W_hh, b_hh,
                                                W_obs_out, isf, t);
        k_gru<<<256, 256>>>(isf, out, t);
        k_out<<<OUT_GEMM + OUT_BG, 256>>>(embed, W_img_out, b_img_out,
                                          W_obs_out, out, t);
        k_sample<<<dim3(256, 2), 256>>>(isf, action, W_img_in, b_img_in,
                                        b_obs_out, out, t);
    }
}

// round 15
// speedup vs baseline: 1.5674x; 1.5674x over previous
#include <cuda_runtime.h>
#include <cstdint>
#include <math.h>

// Problem dimensions
#define BB 256
#define TT 64
#define EE 1024
#define AA 6
#define DD 256
#define SS 32
#define CC 32
#define HH 256
#define SDIM 1024
#define OUTW 4352   // 4*SD + D per (b,t)

#define NGUM (2 * TT * BB * SS * CC)   // 33,554,432 elements

// Precise libdevice logf — direct call bypasses any -use_fast_math macro.
extern "C" __device__ float __nv_logf(float);

// ---------------- device scratch (no allocation allowed) ----------------
__device__ float g_gumbel[NGUM];                    // 134 MB
__device__ float g_deterA[BB * DD];                 // ping-pong deter buffers
__device__ float g_deterB[BB * DD];
__device__ float g_x[BB * HH];                      // GRU input x(t)
__device__ float g_dpart[BB * SDIM];                // deter part of post logits
__device__ float g_epart[(long)BB * TT * SDIM];     // embed part, B-MAJOR [b][t][n]

// ---------------- double-buffered fp32 tiled GEMM core (R7 verbatim) ----
// C[m,n] = sum_{k in [k0,k0+kcnt)} A(m,k)*B[k,n_off+n] (+bias).
// Pure ascending-K per-element accumulation (bit-identical across tilings).
template<int BM, int BN, int BK, int NTHR, class AL>
__device__ __forceinline__ void gemm_db(
    AL aload, const float* __restrict__ Bm, int ldb,
    int m_off, int n_off, int k0, int kcnt,
    float* __restrict__ C, long ldc, const float* __restrict__ bias)
{
    constexpr int APAD = 4;
    __shared__ __align__(16) float As[2][BK][BM + APAD];
    __shared__ __align__(16) float Bs[2][BK][BN];
    const int tid = threadIdx.x;
    constexpr int TM = 4, TN = 4;
    constexpr int NCOL = BN / TN;
    const int tx = tid % NCOL;
    const int ty = tid / NCOL;
    constexpr int ALD = BM * BK / NTHR;
    constexpr int BLD = BN * BK / NTHR;
    const int amk = tid % BK;
    const int am0 = tid / BK;
    const int bn  = tid % BN;
    const int bk0 = tid / BN;

    float rA[ALD], rB[BLD];
    float acc[TM][TN];
#pragma unroll
    for (int i = 0; i < TM; i++)
#pragma unroll
        for (int j = 0; j < TN; j++) acc[i][j] = 0.f;

    const int NT = kcnt / BK;

#pragma unroll
    for (int j = 0; j < ALD; j++)
        rA[j] = aload(m_off + am0 + j * (NTHR / BK), k0 + amk);
#pragma unroll
    for (int j = 0; j < BLD; j++)
        rB[j] = Bm[(long)(k0 + bk0 + j * (NTHR / BN)) * ldb + n_off + bn];
#pragma unroll
    for (int j = 0; j < ALD; j++) As[0][amk][am0 + j * (NTHR / BK)] = rA[j];
#pragma unroll
    for (int j = 0; j < BLD; j++) Bs[0][bk0 + j * (NTHR / BN)][bn] = rB[j];
    __syncthreads();

    for (int kt = 0; kt < NT; kt++) {
        int cur = kt & 1;
        if (kt + 1 < NT) {
            int kb = k0 + (kt + 1) * BK;
#pragma unroll
            for (int j = 0; j < ALD; j++)
                rA[j] = aload(m_off + am0 + j * (NTHR / BK), kb + amk);
#pragma unroll
            for (int j = 0; j < BLD; j++)
                rB[j] = Bm[(long)(kb + bk0 + j * (NTHR / BN)) * ldb + n_off + bn];
        }
#pragma unroll
        for (int kk = 0; kk < BK; kk++) {
            float4 av = *reinterpret_cast<const float4*>(&As[cur][kk][ty * TM]);
            float4 bv = *reinterpret_cast<const float4*>(&Bs[cur][kk][tx * TN]);
            float am[4] = {av.x, av.y, av.z, av.w};
            float bn_[4] = {bv.x, bv.y, bv.z, bv.w};
#pragma unroll
            for (int i = 0; i < TM; i++)
#pragma unroll
                for (int j = 0; j < TN; j++) acc[i][j] += am[i] * bn_[j];
        }
        if (kt + 1 < NT) {
            int nb = cur ^ 1;
#pragma unroll
            for (int j = 0; j < ALD; j++) As[nb][amk][am0 + j * (NTHR / BK)] = rA[j];
#pragma unroll
            for (int j = 0; j < BLD; j++) Bs[nb][bk0 + j * (NTHR / BN)][bn] = rB[j];
            __syncthreads();
        }
    }
#pragma unroll
    for (int i = 0; i < TM; i++) {
        int m = m_off + ty * TM + i;
#pragma unroll
        for (int j = 0; j < TN; j++) {
            int n = n_off + tx * TN + j;
            float v = acc[i][j];
            if (bias) v += bias[n];
            C[(long)m * ldc + n] = v;
        }
    }
}

// ---------------- upfront: embed part of post logits (R7 verbatim) ------
// g_epart[M, n] = sum_e embed[M, e] * W_obs_out[256 + e][n],  M = b*T + t.
__global__ void __launch_bounds__(256, 2)
k_embpart(const float* __restrict__ E, const float* __restrict__ Woo) {
    __shared__ __align__(16) float As[2][8][128 + 4];
    __shared__ __align__(16) float Bs[2][8][128];
    const int tid = threadIdx.x;
    const int N0 = blockIdx.x * 128, M0 = blockIdx.y * 128;
    const int am = tid >> 1, aq = tid & 1;
    const int bk = tid >> 5, bn4 = tid & 31;
    const int tx = tid % 16, ty = tid / 16;

    float4 ra, rb;
    float acc[8][8];
#pragma unroll
    for (int i = 0; i < 8; i++)
#pragma unroll
        for (int j = 0; j < 8; j++) acc[i][j] = 0.f;

    const float* Ap = E + (long)(M0 + am) * EE + aq * 4;
    const float* Bp = Woo + (long)(DD + bk) * SDIM + N0 + bn4 * 4;

    ra = *reinterpret_cast<const float4*>(Ap);
    rb = *reinterpret_cast<const float4*>(Bp);
    As[0][aq * 4 + 0][am] = ra.x; As[0][aq * 4 + 1][am] = ra.y;
    As[0][aq * 4 + 2][am] = ra.z; As[0][aq * 4 + 3][am] = ra.w;
    *reinterpret_cast<float4*>(&Bs[0][bk][bn4 * 4]) = rb;
    __syncthreads();

    for (int kt = 0; kt < 128; kt++) {
        int cur = kt & 1;
        if (kt + 1 < 128) {
            int kb = (kt + 1) * 8;
            ra = *reinterpret_cast<const float4*>(Ap + kb);
            rb = *reinterpret_cast<const float4*>(Bp + (long)kb * SDIM);
        }
#pragma unroll
        for (int kk = 0; kk < 8; kk++) {
            float4 a0 = *reinterpret_cast<const float4*>(&As[cur][kk][ty * 8]);
            float4 a1 = *reinterpret_cast<const float4*>(&As[cur][kk][ty * 8 + 4]);
            float4 b0 = *reinterpret_cast<const float4*>(&Bs[cur][kk][tx * 8]);
            float4 b1 = *reinterpret_cast<const float4*>(&Bs[cur][kk][tx * 8 + 4]);
            float a[8] = {a0.x, a0.y, a0.z, a0.w, a1.x, a1.y, a1.z, a1.w};
            float b[8] = {b0.x, b0.y, b0.z, b0.w, b1.x, b1.y, b1.z, b1.w};
#pragma unroll
            for (int i = 0; i < 8; i++)
#pragma unroll
                for (int j = 0; j < 8; j++) acc[i][j] += a[i] * b[j];
        }
        if (kt + 1 < 128) {
            int nb = cur ^ 1;
            As[nb][aq * 4 + 0][am] = ra.x; As[nb][aq * 4 + 1][am] = ra.y;
            As[nb][aq * 4 + 2][am] = ra.z; As[nb][aq * 4 + 3][am] = ra.w;
            *reinterpret_cast<float4*>(&Bs[nb][bk][bn4 * 4]) = rb;
            __syncthreads();
        }
    }
#pragma unroll
    for (int i = 0; i < 8; i++) {
        long row = (long)(M0 + ty * 8 + i) * SDIM + N0 + tx * 8;
        *reinterpret_cast<float4*>(&g_epart[row])     = make_float4(acc[i][0], acc[i][1], acc[i][2], acc[i][3]);
        *reinterpret_cast<float4*>(&g_epart[row + 4]) = make_float4(acc[i][4], acc[i][5], acc[i][6], acc[i][7]);
    }
}

// ---------------- init + x(0) --------------------------------------------
__global__ void k_init() {
    int i = blockIdx.x * blockDim.x + threadIdx.x;
    g_deterA[i] = 0.f;
}
__global__ void k_x0(const float* __restrict__ action, const float* __restrict__ W1,
                     const float* __restrict__ b1) {
    int b = blockIdx.x, col = threadIdx.x;
    float c3 = 0.f;
#pragma unroll
    for (int a = 0; a < AA; a++)
        c3 = fmaf(action[(long)b * TT * AA + a], W1[(SDIM + a) * HH + col], c3);
    g_x[b * HH + col] = b1[col] + c3;
}

// ---------------- JAX threefry2x32 gumbel (partitionable), fp32 logs ----
__device__ __forceinline__ uint32_t rotl32(uint32_t v, int r) {
    return (v << r) | (v >> (32 - r));
}
__device__ __forceinline__ float bits_to_gumbel(uint32_t b) {
    float u = __uint_as_float((b >> 9) | 0x3f800000u) - 1.0f;
    const float tinyv = 1.17549435e-38f;
    u = fmaxf(u, tinyv);
    float inner = -__nv_logf(u);
    return -__nv_logf(inner);
}
__global__ void k_gumbel() {
    unsigned i = blockIdx.x * blockDim.x + threadIdx.x;
    if (i >= (unsigned)NGUM) return;
    uint32_t x0 = 0u, x1 = i;
    const uint32_t ks0 = 0u, ks1 = 42u, ks2 = 0x1BD11BDAu ^ 0u ^ 42u;
    x0 += ks0; x1 += ks1;
#define TF_R4(a, b, c, d)                                   \
    x0 += x1; x1 = rotl32(x1, a); x1 ^= x0;                 \
    x0 += x1; x1 = rotl32(x1, b); x1 ^= x0;                 \
    x0 += x1; x1 = rotl32(x1, c); x1 ^= x0;                 \
    x0 += x1; x1 = rotl32(x1, d); x1 ^= x0;
    TF_R4(13, 15, 26, 6);  x0 += ks1; x1 += ks2 + 1u;
    TF_R4(17, 29, 16, 24); x0 += ks2; x1 += ks0 + 2u;
    TF_R4(13, 15, 26, 6);  x0 += ks0; x1 += ks1 + 3u;
    TF_R4(17, 29, 16, 24); x0 += ks1; x1 += ks2 + 4u;
    TF_R4(13, 15, 26, 6);  x0 += ks2; x1 += ks0 + 5u;
#undef TF_R4
    g_gumbel[i] = bits_to_gumbel(x0 ^ x1);
}

// ---------------- precise transcendentals (double; proven) ---------------
__device__ __forceinline__ float sigm_precise(float x) {
    return (float)(1.0 / (1.0 + exp((double)(-x))));
}
__device__ __forceinline__ float tanh_precise(float x) {
    return (float)tanh((double)x);
}

// ---------------- fused gates + GRU (R10 verbatim — proven bit-exact) ----
__global__ void __launch_bounds__(256)
k_gatesgru(const float* __restrict__ Wih, const float* __restrict__ bih,
           const float* __restrict__ Whh, const float* __restrict__ bhh,
           const float* __restrict__ isf,
           float* __restrict__ out, int t)
{
    const float* dold = (t & 1) ? g_deterB : g_deterA;
    float*       dnew = (t & 1) ? g_deterA : g_deterB;

    constexpr int BM = 32, BN = 32, BK = 16;
    __shared__ __align__(16) float Ax[2][BK][BM + 2];
    __shared__ __align__(16) float Ah[2][BK][BM + 2];
    __shared__ __align__(16) float Bs[6][2][BK][BN];

    const int tid = threadIdx.x;
    const int d0 = blockIdx.x * BN;
    const int m0 = blockIdx.y * BM;
    const int tx = tid % 16, ty = tid / 16;

    const int amk = tid % 16, am0 = tid / 16;
    const int bn = tid % 32, bk0 = tid / 32;

    float aiR[2][2], aiZ[2][2], aiN[2][2], ahR[2][2], ahZ[2][2], ahN[2][2];
#pragma unroll
    for (int i = 0; i < 2; i++)
#pragma unroll
        for (int j = 0; j < 2; j++) {
            aiR[i][j] = aiZ[i][j] = aiN[i][j] = 0.f;
            ahR[i][j] = ahZ[i][j] = ahN[i][j] = 0.f;
        }

    float rx[2], rh[2], rb[6][2];
#pragma unroll
    for (int p = 0; p < 2; p++) {
        int m = m0 + am0 + p * 16;
        rx[p] = g_x[m * HH + amk];
        rh[p] = dold[m * DD + amk] * (1.0f - isf[m * TT + t]);
    }
#pragma unroll
    for (int g = 0; g < 6; g++) {
        const float* W = (g < 3) ? Wih : Whh;
        int nc = (g % 3) * 256 + d0 + bn;
#pragma unroll
        for (int p = 0; p < 2; p++)
            rb[g][p] = W[(bk0 + p * 8) * 768 + nc];
    }
#pragma unroll
    for (int p = 0; p < 2; p++) {
        Ax[0][amk][am0 + p * 16] = rx[p];
        Ah[0][amk][am0 + p * 16] = rh[p];
    }
#pragma unroll
    for (int g = 0; g < 6; g++)
#pragma unroll
        for (int p = 0; p < 2; p++)
            Bs[g][0][bk0 + p * 8][bn] = rb[g][p];
    __syncthreads();

    for (int kt = 0; kt < DD / BK; kt++) {
        int cur = kt & 1;
        if (kt + 1 < DD / BK) {
            int kb = (kt + 1) * BK;
#pragma unroll
            for (int p = 0; p < 2; p++) {
                int m = m0 + am0 + p * 16;
                rx[p] = g_x[m * HH + kb + amk];
                rh[p] = dold[m * DD + kb + amk] * (1.0f - isf[m * TT + t]);
            }
#pragma unroll
            for (int g = 0; g < 6; g++) {
                const float* W = (g < 3) ? Wih : Whh;
                int nc = (g % 3) * 256 + d0 + bn;
#pragma unroll
                for (int p = 0; p < 2; p++)
                    rb[g][p] = W[(kb + bk0 + p * 8) * 768 + nc];
            }
        }
#pragma unroll
        for (int kk = 0; kk < BK; kk++) {
            float ax0 = Ax[cur][kk][ty * 2], ax1 = Ax[cur][kk][ty * 2 + 1];
            float ah0 = Ah[cur][kk][ty * 2], ah1 = Ah[cur][kk][ty * 2 + 1];
            float bR0 = Bs[0][cur][kk][tx * 2], bR1 = Bs[0][cur][kk][tx * 2 + 1];
            float bZ0 = Bs[1][cur][kk][tx * 2], bZ1 = Bs[1][cur][kk][tx * 2 + 1];
            float bN0 = Bs[2][cur][kk][tx * 2], bN1 = Bs[2][cur][kk][tx * 2 + 1];
            float cR0 = Bs[3][cur][kk][tx * 2], cR1 = Bs[3][cur][kk][tx * 2 + 1];
            float cZ0 = Bs[4][cur][kk][tx * 2], cZ1 = Bs[4][cur][kk][tx * 2 + 1];
            float cN0 = Bs[5][cur][kk][tx * 2], cN1 = Bs[5][cur][kk][tx * 2 + 1];
            aiR[0][0] += ax0 * bR0; aiR[0][1] += ax0 * bR1;
            aiR[1][0] += ax1 * bR0; aiR[1][1] += ax1 * bR1;
            aiZ[0][0] += ax0 * bZ0; aiZ[0][1] += ax0 * bZ1;
            aiZ[1][0] += ax1 * bZ0; aiZ[1][1] += ax1 * bZ1;
            aiN[0][0] += ax0 * bN0; aiN[0][1] += ax0 * bN1;
            aiN[1][0] += ax1 * bN0; aiN[1][1] += ax1 * bN1;
            ahR[0][0] += ah0 * cR0; ahR[0][1] += ah0 * cR1;
            ahR[1][0] += ah1 * cR0; ahR[1][1] += ah1 * cR1;
            ahZ[0][0] += ah0 * cZ0; ahZ[0][1] += ah0 * cZ1;
            ahZ[1][0] += ah1 * cZ0; ahZ[1][1] += ah1 * cZ1;
            ahN[0][0] += ah0 * cN0; ahN[0][1] += ah0 * cN1;
            ahN[1][0] += ah1 * cN0; ahN[1][1] += ah1 * cN1;
        }
        if (kt + 1 < DD / BK) {
            int nb = cur ^ 1;
#pragma unroll
            for (int p = 0; p < 2; p++) {
                Ax[nb][amk][am0 + p * 16] = rx[p];
                Ah[nb][amk][am0 + p * 16] = rh[p];
            }
#pragma unroll
            for (int g = 0; g < 6; g++)
#pragma unroll
                for (int p = 0; p < 2; p++)
                    Bs[g][nb][bk0 + p * 8][bn] = rb[g][p];
            __syncthreads();
        }
    }

    // exact GRU epilogue
#pragma unroll
    for (int i = 0; i < 2; i++) {
        int m = m0 + ty * 2 + i;
        float mask = 1.0f - isf[m * TT + t];
#pragma unroll
        for (int j = 0; j < 2; j++) {
            int d = d0 + tx * 2 + j;
            float ir = aiR[i][j] + bih[d];
            float iz = aiZ[i][j] + bih[256 + d];
            float in_ = aiN[i][j] + bih[512 + d];
            float hr = ahR[i][j] + bhh[d];
            float hz = ahZ[i][j] + bhh[256 + d];
            float hn = ahN[i][j] + bhh[512 + d];
            float r = sigm_precise(ir + hr);
            float z = sigm_precise(iz + hz);
            float n = tanh_precise(in_ + r * hn);
            float h = dold[m * DD + d] * mask;
            float nd = (1.0f - z) * n + z * h;
            dnew[m * DD + d] = nd;
            out[((long)m * TT + t) * OUTW + 2048 + d] = nd;
        }
    }
}

// ---------------- prior + dpart GEMMs (R10 verbatim) ---------------------
struct DetP {
    const float* d;
    __device__ float operator()(int m, int k) const { return d[m * DD + k]; }
};
__global__ void __launch_bounds__(256)
k_out(const float* __restrict__ Wio, const float* __restrict__ bio,
      const float* __restrict__ Woo, float* __restrict__ out, int t) {
    const float* det = (t & 1) ? g_deterA : g_deterB;   // = dnew of step t
    if (blockIdx.z == 0)
        gemm_db<64, 64, 16, 256>(DetP{det}, Wio, SDIM,
                                 blockIdx.y * 64, blockIdx.x * 64, 0, DD,
                                 out + (long)t * OUTW + 2304, (long)TT * OUTW, bio);
    else
        gemm_db<64, 64, 16, 256>(DetP{det}, Woo, SDIM,
                                 blockIdx.y * 64, blockIdx.x * 64, 0, DD,
                                 g_dpart, SDIM, nullptr);
}

// ---------------- sampling + x feedback (R7 verbatim) --------------------
__global__ void k_sample(const float* __restrict__ isf, const float* __restrict__ action,
                         const float* __restrict__ W1, const float* __restrict__ b1,
                         const float* __restrict__ boo, float* __restrict__ out, int t) {
    int b = blockIdx.x;
    int draw = blockIdx.y;
    int tid = threadIdx.x, lane = tid & 31, w = tid >> 5;
    __shared__ int sidx[SS];
    long obase = ((long)b * TT + t) * OUTW;

#pragma unroll
    for (int q = 0; q < 4; q++) {
        int g = w * 4 + q;
        int col = g * 32 + lane;
        float lv;
        if (draw == 0) {
            lv = out[obase + 2304 + col];
        } else {
            lv = (g_dpart[b * SDIM + col] + g_epart[((long)b * TT + t) * SDIM + col]) + boo[col];
            out[obase + col] = lv;
        }
        float gum = g_gumbel[(((long)draw * TT + t) * BB + b) * SDIM + col];
        float v = lv + gum;
        int idx = lane;
#pragma unroll
        for (int off = 16; off > 0; off >>= 1) {
            float v2 = __shfl_xor_sync(0xffffffffu, v, off);
            int i2 = __shfl_xor_sync(0xffffffffu, idx, off);
            if (v2 > v || (v2 == v && i2 < idx)) { v = v2; idx = i2; }
        }
        float oh = (lane == idx) ? 1.0f : 0.0f;
        out[obase + (draw ? 1024 : 3328) + col] = oh;
        if (draw && lane == 0) sidx[g] = idx;
    }

    if (draw == 1 && t + 1 < TT) {
        __syncthreads();
        int col = tid;
        float mask = 1.0f - isf[b * TT + (t + 1)];
        float c0 = 0.f, c1 = 0.f, c2 = 0.f, c3 = 0.f;
        int i8 = sidx[8], i25 = sidx[25];
#pragma unroll
        for (int s2 = 0; s2 < 8; s2++)
            c0 = fmaf(mask, W1[(s2 * 32 + sidx[s2]) * HH + col], c0);
        {
            float wv = W1[(8 * 32 + i8) * HH + col];
            if (i8 < 16) c0 = fmaf(mask, wv, c0); else c1 = fmaf(mask, wv, c1);
        }
#pragma unroll
        for (int s2 = 9; s2 < 17; s2++)
            c1 = fmaf(mask, W1[(s2 * 32 + sidx[s2]) * HH + col], c1);
#pragma unroll
        for (int s2 = 17; s2 < 25; s2++)
            c2 = fmaf(mask, W1[(s2 * 32 + sidx[s2]) * HH + col], c2);
        {
            float wv = W1[(25 * 32 + i25) * HH + col];
            if (i25 < 16) c2 = fmaf(mask, wv, c2); else c3 = fmaf(mask, wv, c3);
        }
#pragma unroll
        for (int s2 = 26; s2 < 32; s2++)
            c3 = fmaf(mask, W1[(s2 * 32 + sidx[s2]) * HH + col], c3);
#pragma unroll
        for (int a = 0; a < AA; a++)
            c3 = fmaf(action[((long)b * TT + (t + 1)) * AA + a],
                      W1[(SDIM + a) * HH + col], c3);
        g_x[b * HH + col] = (((c0 + b1[col]) + c1) + c2) + c3;
    }
}

// ---------------- launch ----------------
extern "C" void kernel_launch(void* const* d_in, const int* in_sizes, int n_in,
                              void* d_out, int out_size) {
    (void)in_sizes; (void)n_in; (void)out_size;
    const float* embed     = (const float*)d_in[0];
    const float* action    = (const float*)d_in[1];
    const float* isf       = (const float*)d_in[2];
    const float* W_img_in  = (const float*)d_in[3];
    const float* b_img_in  = (const float*)d_in[4];
    const float* W_ih      = (const float*)d_in[5];
    const float* b_ih      = (const float*)d_in[6];
    const float* W_hh      = (const float*)d_in[7];
    const float* b_hh      = (const float*)d_in[8];
    const float* W_img_out = (const float*)d_in[9];
    const float* b_img_out = (const float*)d_in[10];
    const float* W_obs_out = (const float*)d_in[11];
    const float* b_obs_out = (const float*)d_in[12];
    float* out = (float*)d_out;

    k_embpart<<<dim3(8, 128), 256>>>(embed, W_obs_out);
    k_gumbel<<<NGUM / 256, 256>>>();
    k_init<<<256, 256>>>();
    k_x0<<<256, 256>>>(action, W_img_in, b_img_in);
    for (int t = 0; t < TT; t++) {
        k_gatesgru<<<dim3(8, 8), 256>>>(W_ih, b_ih, W_hh, b_hh, isf, out, t);
        k_out<<<dim3(16, 4, 2), 256>>>(W_img_out, b_img_out, W_obs_out, out, t);
        k_sample<<<dim3(256, 2), 256>>>(isf, action, W_img_in, b_img_in,
                                        b_obs_out, out, t);
    }
}

// round 16
// speedup vs baseline: 1.8203x; 1.1614x over previous
#include <cuda_runtime.h>
#include <cstdint>
#include <math.h>

// Problem dimensions
#define BB 256
#define TT 64
#define EE 1024
#define AA 6
#define DD 256
#define SS 32
#define CC 32
#define HH 256
#define SDIM 1024
#define OUTW 4352   // 4*SD + D per (b,t)

#define NGUM (2 * TT * BB * SS * CC)   // 4,194,304 elements

// Precise libdevice math — direct calls bypass any -use_fast_math macros.
extern "C" __device__ float __nv_logf(float);
extern "C" __device__ float __nv_expf(float);
extern "C" __device__ float __nv_tanhf(float);

// ---------------- device scratch (no allocation allowed) ----------------
__device__ float g_gumbel[NGUM];
__device__ float g_deter[BB * DD];
__device__ float g_x[BB * HH];                      // GRU input x(t)
__device__ float g_gi[BB * 768];
__device__ float g_gh[BB * 768];
__device__ float g_dpart[BB * SDIM];                // deter part of post logits
__device__ float g_epart[(long)BB * TT * SDIM];     // embed part, B-MAJOR [b][t][n]

// ---------------- double-buffered fp32 tiled GEMM core ------------------
// C[m,n] = sum_{k in [k0,k0+kcnt)} A(m,k)*B[k,n_off+n] (+bias).
// Pure ascending-K per-element accumulation (bit-identical across tilings).
template<int BM, int BN, int BK, int NTHR, class AL>
__device__ __forceinline__ void gemm_db(
    AL aload, const float* __restrict__ Bm, int ldb,
    int m_off, int n_off, int k0, int kcnt,
    float* __restrict__ C, long ldc, const float* __restrict__ bias)
{
    constexpr int APAD = 4;
    __shared__ __align__(16) float As[2][BK][BM + APAD];
    __shared__ __align__(16) float Bs[2][BK][BN];
    const int tid = threadIdx.x;
    constexpr int TM = 4, TN = 4;
    constexpr int NCOL = BN / TN;
    const int tx = tid % NCOL;
    const int ty = tid / NCOL;
    constexpr int ALD = BM * BK / NTHR;
    constexpr int BLD = BN * BK / NTHR;
    const int amk = tid % BK;
    const int am0 = tid / BK;
    const int bn  = tid % BN;
    const int bk0 = tid / BN;

    float rA[ALD], rB[BLD];
    float acc[TM][TN];
#pragma unroll
    for (int i = 0; i < TM; i++)
#pragma unroll
        for (int j = 0; j < TN; j++) acc[i][j] = 0.f;

    const int NT = kcnt / BK;

#pragma unroll
    for (int j = 0; j < ALD; j++)
        rA[j] = aload(m_off + am0 + j * (NTHR / BK), k0 + amk);
#pragma unroll
    for (int j = 0; j < BLD; j++)
        rB[j] = Bm[(long)(k0 + bk0 + j * (NTHR / BN)) * ldb + n_off + bn];
#pragma unroll
    for (int j = 0; j < ALD; j++) As[0][amk][am0 + j * (NTHR / BK)] = rA[j];
#pragma unroll
    for (int j = 0; j < BLD; j++) Bs[0][bk0 + j * (NTHR / BN)][bn] = rB[j];
    __syncthreads();

    for (int kt = 0; kt < NT; kt++) {
        int cur = kt & 1;
        if (kt + 1 < NT) {
            int kb = k0 + (kt + 1) * BK;
#pragma unroll
            for (int j = 0; j < ALD; j++)
                rA[j] = aload(m_off + am0 + j * (NTHR / BK), kb + amk);
#pragma unroll
            for (int j = 0; j < BLD; j++)
                rB[j] = Bm[(long)(kb + bk0 + j * (NTHR / BN)) * ldb + n_off + bn];
        }
#pragma unroll
        for (int kk = 0; kk < BK; kk++) {
            float4 av = *reinterpret_cast<const float4*>(&As[cur][kk][ty * TM]);
            float4 bv = *reinterpret_cast<const float4*>(&Bs[cur][kk][tx * TN]);
            float am[4] = {av.x, av.y, av.z, av.w};
            float bn_[4] = {bv.x, bv.y, bv.z, bv.w};
#pragma unroll
            for (int i = 0; i < TM; i++)
#pragma unroll
                for (int j = 0; j < TN; j++) acc[i][j] += am[i] * bn_[j];
        }
        if (kt + 1 < NT) {
            int nb = cur ^ 1;
#pragma unroll
            for (int j = 0; j < ALD; j++) As[nb][amk][am0 + j * (NTHR / BK)] = rA[j];
#pragma unroll
            for (int j = 0; j < BLD; j++) Bs[nb][bk0 + j * (NTHR / BN)][bn] = rB[j];
            __syncthreads();
        }
    }
#pragma unroll
    for (int i = 0; i < TM; i++) {
        int m = m_off + ty * TM + i;
#pragma unroll
        for (int j = 0; j < TN; j++) {
            int n = n_off + tx * TN + j;
            float v = acc[i][j];
            if (bias) v += bias[n];
            C[(long)m * ldc + n] = v;
        }
    }
}

// ---------------- upfront: embed part of post logits (R7 verbatim) ------
// g_epart[M, n] = sum_e embed[M, e] * W_obs_out[256 + e][n],  M = b*T + t.
__global__ void __launch_bounds__(256, 2)
k_embpart(const float* __restrict__ E, const float* __restrict__ Woo) {
    __shared__ __align__(16) float As[2][8][128 + 4];
    __shared__ __align__(16) float Bs[2][8][128];
    const int tid = threadIdx.x;
    const int N0 = blockIdx.x * 128, M0 = blockIdx.y * 128;
    const int am = tid >> 1, aq = tid & 1;
    const int bk = tid >> 5, bn4 = tid & 31;
    const int tx = tid % 16, ty = tid / 16;

    float4 ra, rb;
    float acc[8][8];
#pragma unroll
    for (int i = 0; i < 8; i++)
#pragma unroll
        for (int j = 0; j < 8; j++) acc[i][j] = 0.f;

    const float* Ap = E + (long)(M0 + am) * EE + aq * 4;
    const float* Bp = Woo + (long)(DD + bk) * SDIM + N0 + bn4 * 4;

    ra = *reinterpret_cast<const float4*>(Ap);
    rb = *reinterpret_cast<const float4*>(Bp);
    As[0][aq * 4 + 0][am] = ra.x; As[0][aq * 4 + 1][am] = ra.y;
    As[0][aq * 4 + 2][am] = ra.z; As[0][aq * 4 + 3][am] = ra.w;
    *reinterpret_cast<float4*>(&Bs[0][bk][bn4 * 4]) = rb;
    __syncthreads();

    for (int kt = 0; kt < 128; kt++) {
        int cur = kt & 1;
        if (kt + 1 < 128) {
            int kb = (kt + 1) * 8;
            ra = *reinterpret_cast<const float4*>(Ap + kb);
            rb = *reinterpret_cast<const float4*>(Bp + (long)kb * SDIM);
        }
#pragma unroll
        for (int kk = 0; kk < 8; kk++) {
            float4 a0 = *reinterpret_cast<const float4*>(&As[cur][kk][ty * 8]);
            float4 a1 = *reinterpret_cast<const float4*>(&As[cur][kk][ty * 8 + 4]);
            float4 b0 = *reinterpret_cast<const float4*>(&Bs[cur][kk][tx * 8]);
            float4 b1 = *reinterpret_cast<const float4*>(&Bs[cur][kk][tx * 8 + 4]);
            float a[8] = {a0.x, a0.y, a0.z, a0.w, a1.x, a1.y, a1.z, a1.w};
            float b[8] = {b0.x, b0.y, b0.z, b0.w, b1.x, b1.y, b1.z, b1.w};
#pragma unroll
            for (int i = 0; i < 8; i++)
#pragma unroll
                for (int j = 0; j < 8; j++) acc[i][j] += a[i] * b[j];
        }
        if (kt + 1 < 128) {
            int nb = cur ^ 1;
            As[nb][aq * 4 + 0][am] = ra.x; As[nb][aq * 4 + 1][am] = ra.y;
            As[nb][aq * 4 + 2][am] = ra.z; As[nb][aq * 4 + 3][am] = ra.w;
            *reinterpret_cast<float4*>(&Bs[nb][bk][bn4 * 4]) = rb;
            __syncthreads();
        }
    }
#pragma unroll
    for (int i = 0; i < 8; i++) {
        long row = (long)(M0 + ty * 8 + i) * SDIM + N0 + tx * 8;
        *reinterpret_cast<float4*>(&g_epart[row])     = make_float4(acc[i][0], acc[i][1], acc[i][2], acc[i][3]);
        *reinterpret_cast<float4*>(&g_epart[row + 4]) = make_float4(acc[i][4], acc[i][5], acc[i][6], acc[i][7]);
    }
}

// ---------------- init + x(0) --------------------------------------------
__global__ void k_init() {
    int i = blockIdx.x * blockDim.x + threadIdx.x;
    g_deter[i] = 0.f;
}
__global__ void k_x0(const float* __restrict__ action, const float* __restrict__ W1,
                     const float* __restrict__ b1) {
    int b = blockIdx.x, col = threadIdx.x;
    float c3 = 0.f;
#pragma unroll
    for (int a = 0; a < AA; a++)
        c3 = fmaf(action[(long)b * TT * AA + a], W1[(SDIM + a) * HH + col], c3);
    g_x[b * HH + col] = b1[col] + c3;
}

// ---------------- JAX threefry2x32 gumbel (partitionable), fp32 logs ----
// fp32 __nv_logf proven flip-free in R15 (rel_err identical to double-log R7).
__device__ __forceinline__ uint32_t rotl32(uint32_t v, int r) {
    return (v << r) | (v >> (32 - r));
}
__device__ __forceinline__ float bits_to_gumbel(uint32_t b) {
    float u = __uint_as_float((b >> 9) | 0x3f800000u) - 1.0f;
    const float tinyv = 1.17549435e-38f;
    u = fmaxf(u, tinyv);
    float inner = -__nv_logf(u);
    return -__nv_logf(inner);
}
__global__ void k_gumbel() {
    unsigned i = blockIdx.x * blockDim.x + threadIdx.x;
    if (i >= (unsigned)NGUM) return;
    uint32_t x0 = 0u, x1 = i;
    const uint32_t ks0 = 0u, ks1 = 42u, ks2 = 0x1BD11BDAu ^ 0u ^ 42u;
    x0 += ks0; x1 += ks1;
#define TF_R4(a, b, c, d)                                   \
    x0 += x1; x1 = rotl32(x1, a); x1 ^= x0;                 \
    x0 += x1; x1 = rotl32(x1, b); x1 ^= x0;                 \
    x0 += x1; x1 = rotl32(x1, c); x1 ^= x0;                 \
    x0 += x1; x1 = rotl32(x1, d); x1 ^= x0;
    TF_R4(13, 15, 26, 6);  x0 += ks1; x1 += ks2 + 1u;
    TF_R4(17, 29, 16, 24); x0 += ks2; x1 += ks0 + 2u;
    TF_R4(13, 15, 26, 6);  x0 += ks0; x1 += ks1 + 3u;
    TF_R4(17, 29, 16, 24); x0 += ks1; x1 += ks2 + 4u;
    TF_R4(13, 15, 26, 6);  x0 += ks2; x1 += ks0 + 5u;
#undef TF_R4
    g_gumbel[i] = bits_to_gumbel(x0 ^ x1);
}

// ---------------- step kernels -------------------------------------------
// Gates GEMMs: 64x32 tiles, 128 threads -> 192 blocks (bit-identical math).
struct GiL {
    __device__ float operator()(int m, int k) const { return g_x[m * HH + k]; }
};
struct GhL {
    const float* isf; int t;
    __device__ float operator()(int m, int k) const {
        return g_deter[m * DD + k] * (1.0f - isf[m * TT + t]);
    }
};
__global__ void __launch_bounds__(128)
k_gates(const float* __restrict__ Wih, const float* __restrict__ bih,
        const float* __restrict__ Whh, const float* __restrict__ bhh,
        const float* __restrict__ isf, int t) {
    if (blockIdx.z == 0)
        gemm_db<64, 32, 16, 128>(GiL{}, Wih, 768,
                                 blockIdx.y * 64, blockIdx.x * 32, 0, DD, g_gi, 768, bih);
    else
        gemm_db<64, 32, 16, 128>(GhL{isf, t}, Whh, 768,
                                 blockIdx.y * 64, blockIdx.x * 32, 0, DD, g_gh, 768, bhh);
}

// GRU combine (fp32 libdevice transcendentals; ~1-ulp gamble).
__device__ __forceinline__ float sigm_f(float x) {
    return 1.0f / (1.0f + __nv_expf(-x));
}
__global__ void k_gru(const float* __restrict__ isf, float* __restrict__ out, int t) {
    int i = blockIdx.x * blockDim.x + threadIdx.x;
    int b = i >> 8, d = i & 255;
    float ir = g_gi[b * 768 + d], iz = g_gi[b * 768 + 256 + d], in_ = g_gi[b * 768 + 512 + d];
    float hr = g_gh[b * 768 + d], hz = g_gh[b * 768 + 256 + d], hn = g_gh[b * 768 + 512 + d];
    float r = sigm_f(ir + hr);
    float z = sigm_f(iz + hz);
    float n = __nv_tanhf(in_ + r * hn);
    float h = g_deter[i] * (1.0f - isf[b * TT + t]);
    float nd = (1.0f - z) * n + z * h;
    g_deter[i] = nd;
    out[((long)b * TT + t) * OUTW + 2048 + d] = nd;
}

// Out GEMMs: 64x32 tiles, 128 threads -> 256 blocks (bit-identical math).
struct DetL {
    __device__ float operator()(int m, int k) const { return g_deter[m * DD + k]; }
};
__global__ void __launch_bounds__(128)
k_out(const float* __restrict__ Wio, const float* __restrict__ bio,
      const float* __restrict__ Woo, float* __restrict__ out, int t) {
    if (blockIdx.z == 0)
        gemm_db<64, 32, 16, 128>(DetL{}, Wio, SDIM,
                                 blockIdx.y * 64, blockIdx.x * 32, 0, DD,
                                 out + (long)t * OUTW + 2304, (long)TT * OUTW, bio);
    else
        gemm_db<64, 32, 16, 128>(DetL{}, Woo, SDIM,
                                 blockIdx.y * 64, blockIdx.x * 32, 0, DD,
                                 g_dpart, SDIM, nullptr);
}

// ---------------- sampling + x feedback (R7 verbatim) --------------------
__global__ void k_sample(const float* __restrict__ isf, const float* __restrict__ action,
                         const float* __restrict__ W1, const float* __restrict__ b1,
                         const float* __restrict__ boo, float* __restrict__ out, int t) {
    int b = blockIdx.x;
    int draw = blockIdx.y;
    int tid = threadIdx.x, lane = tid & 31, w = tid >> 5;
    __shared__ int sidx[SS];
    long obase = ((long)b * TT + t) * OUTW;

#pragma unroll
    for (int q = 0; q < 4; q++) {
        int g = w * 4 + q;
        int col = g * 32 + lane;
        float lv;
        if (draw == 0) {
            lv = out[obase + 2304 + col];
        } else {
            lv = (g_dpart[b * SDIM + col] + g_epart[((long)b * TT + t) * SDIM + col]) + boo[col];
            out[obase + col] = lv;
        }
        float gum = g_gumbel[(((long)draw * TT + t) * BB + b) * SDIM + col];
        float v = lv + gum;
        int idx = lane;
#pragma unroll
        for (int off = 16; off > 0; off >>= 1) {
            float v2 = __shfl_xor_sync(0xffffffffu, v, off);
            int i2 = __shfl_xor_sync(0xffffffffu, idx, off);
            if (v2 > v || (v2 == v && i2 < idx)) { v = v2; idx = i2; }
        }
        float oh = (lane == idx) ? 1.0f : 0.0f;
        out[obase + (draw ? 1024 : 3328) + col] = oh;
        if (draw && lane == 0) sidx[g] = idx;
    }

    if (draw == 1 && t + 1 < TT) {
        __syncthreads();
        int col = tid;
        float mask = 1.0f - isf[b * TT + (t + 1)];
        float c0 = 0.f, c1 = 0.f, c2 = 0.f, c3 = 0.f;
        int i8 = sidx[8], i25 = sidx[25];
#pragma unroll
        for (int s2 = 0; s2 < 8; s2++)
            c0 = fmaf(mask, W1[(s2 * 32 + sidx[s2]) * HH + col], c0);
        {
            float wv = W1[(8 * 32 + i8) * HH + col];
            if (i8 < 16) c0 = fmaf(mask, wv, c0); else c1 = fmaf(mask, wv, c1);
        }
#pragma unroll
        for (int s2 = 9; s2 < 17; s2++)
            c1 = fmaf(mask, W1[(s2 * 32 + sidx[s2]) * HH + col], c1);
#pragma unroll
        for (int s2 = 17; s2 < 25; s2++)
            c2 = fmaf(mask, W1[(s2 * 32 + sidx[s2]) * HH + col], c2);
        {
            float wv = W1[(25 * 32 + i25) * HH + col];
            if (i25 < 16) c2 = fmaf(mask, wv, c2); else c3 = fmaf(mask, wv, c3);
        }
#pragma unroll
        for (int s2 = 26; s2 < 32; s2++)
            c3 = fmaf(mask, W1[(s2 * 32 + sidx[s2]) * HH + col], c3);
#pragma unroll
        for (int a = 0; a < AA; a++)
            c3 = fmaf(action[((long)b * TT + (t + 1)) * AA + a],
                      W1[(SDIM + a) * HH + col], c3);
        g_x[b * HH + col] = (((c0 + b1[col]) + c1) + c2) + c3;
    }
}

// ---------------- launch ----------------
extern "C" void kernel_launch(void* const* d_in, const int* in_sizes, int n_in,
                              void* d_out, int out_size) {
    (void)in_sizes; (void)n_in; (void)out_size;
    const float* embed     = (const float*)d_in[0];
    const float* action    = (const float*)d_in[1];
    const float* isf       = (const float*)d_in[2];
    const float* W_img_in  = (const float*)d_in[3];
    const float* b_img_in  = (const float*)d_in[4];
    const float* W_ih      = (const float*)d_in[5];
    const float* b_ih      = (const float*)d_in[6];
    const float* W_hh      = (const float*)d_in[7];
    const float* b_hh      = (const float*)d_in[8];
    const float* W_img_out = (const float*)d_in[9];
    const float* b_img_out = (const float*)d_in[10];
    const float* W_obs_out = (const float*)d_in[11];
    const float* b_obs_out = (const float*)d_in[12];
    float* out = (float*)d_out;

    k_embpart<<<dim3(8, 128), 256>>>(embed, W_obs_out);
    k_gumbel<<<NGUM / 256, 256>>>();
    k_init<<<256, 256>>>();
    k_x0<<<256, 256>>>(action, W_img_in, b_img_in);
    for (int t = 0; t < TT; t++) {
        k_gates<<<dim3(24, 4, 2), 128>>>(W_ih, b_ih, W_hh, b_hh, isf, t);
        k_gru<<<256, 256>>>(isf, out, t);
        k_out<<<dim3(32, 4, 2), 128>>>(W_img_out, b_img_out, W_obs_out, out, t);
        k_sample<<<dim3(256, 2), 256>>>(isf, action, W_img_in, b_img_in,
                                        b_obs_out, out, t);
    }
}

// round 17
// speedup vs baseline: 1.8664x; 1.0253x over previous
#include <cuda_runtime.h>
#include <cstdint>
#include <math.h>

// Problem dimensions
#define BB 256
#define TT 64
#define EE 1024
#define AA 6
#define DD 256
#define SS 32
#define CC 32
#define HH 256
#define SDIM 1024
#define OUTW 4352   // 4*SD + D per (b,t)

#define NGUM (2 * TT * BB * SS * CC)   // 4,194,304 elements

// Precise libdevice math — direct calls bypass any -use_fast_math macros.
extern "C" __device__ float __nv_logf(float);
extern "C" __device__ float __nv_expf(float);
extern "C" __device__ float __nv_tanhf(float);

// ---------------- device scratch (no allocation allowed) ----------------
__device__ float g_gumbel[NGUM];
__device__ float g_deter[BB * DD];
__device__ float g_x[BB * HH];                      // GRU input x(t)
__device__ float g_gi[BB * 768];
__device__ float g_gh[BB * 768];
__device__ float g_dpart[BB * SDIM];                // deter part of post logits
__device__ float g_epart[(long)BB * TT * SDIM];     // embed part, B-MAJOR [b][t][n]
__device__ unsigned g_c1;                           // monotonic barrier counter

// ---------------- double-buffered fp32 tiled GEMM core (R7 verbatim) ----
// C[m,n] = sum_{k in [k0,k0+kcnt)} A(m,k)*B[k,n_off+n] (+bias).
// Pure ascending-K per-element accumulation (bit-identical across tilings).
template<int BM, int BN, int BK, int NTHR, class AL>
__device__ __forceinline__ void gemm_db(
    AL aload, const float* __restrict__ Bm, int ldb,
    int m_off, int n_off, int k0, int kcnt,
    float* __restrict__ C, long ldc, const float* __restrict__ bias)
{
    constexpr int APAD = 4;
    __shared__ __align__(16) float As[2][BK][BM + APAD];
    __shared__ __align__(16) float Bs[2][BK][BN];
    const int tid = threadIdx.x;
    constexpr int TM = 4, TN = 4;
    constexpr int NCOL = BN / TN;
    const int tx = tid % NCOL;
    const int ty = tid / NCOL;
    constexpr int ALD = BM * BK / NTHR;
    constexpr int BLD = BN * BK / NTHR;
    const int amk = tid % BK;
    const int am0 = tid / BK;
    const int bn  = tid % BN;
    const int bk0 = tid / BN;

    float rA[ALD], rB[BLD];
    float acc[TM][TN];
#pragma unroll
    for (int i = 0; i < TM; i++)
#pragma unroll
        for (int j = 0; j < TN; j++) acc[i][j] = 0.f;

    const int NT = kcnt / BK;

#pragma unroll
    for (int j = 0; j < ALD; j++)
        rA[j] = aload(m_off + am0 + j * (NTHR / BK), k0 + amk);
#pragma unroll
    for (int j = 0; j < BLD; j++)
        rB[j] = Bm[(long)(k0 + bk0 + j * (NTHR / BN)) * ldb + n_off + bn];
#pragma unroll
    for (int j = 0; j < ALD; j++) As[0][amk][am0 + j * (NTHR / BK)] = rA[j];
#pragma unroll
    for (int j = 0; j < BLD; j++) Bs[0][bk0 + j * (NTHR / BN)][bn] = rB[j];
    __syncthreads();

    for (int kt = 0; kt < NT; kt++) {
        int cur = kt & 1;
        if (kt + 1 < NT) {
            int kb = k0 + (kt + 1) * BK;
#pragma unroll
            for (int j = 0; j < ALD; j++)
                rA[j] = aload(m_off + am0 + j * (NTHR / BK), kb + amk);
#pragma unroll
            for (int j = 0; j < BLD; j++)
                rB[j] = Bm[(long)(kb + bk0 + j * (NTHR / BN)) * ldb + n_off + bn];
        }
#pragma unroll
        for (int kk = 0; kk < BK; kk++) {
            float4 av = *reinterpret_cast<const float4*>(&As[cur][kk][ty * TM]);
            float4 bv = *reinterpret_cast<const float4*>(&Bs[cur][kk][tx * TN]);
            float am[4] = {av.x, av.y, av.z, av.w};
            float bn_[4] = {bv.x, bv.y, bv.z, bv.w};
#pragma unroll
            for (int i = 0; i < TM; i++)
#pragma unroll
                for (int j = 0; j < TN; j++) acc[i][j] += am[i] * bn_[j];
        }
        if (kt + 1 < NT) {
            int nb = cur ^ 1;
#pragma unroll
            for (int j = 0; j < ALD; j++) As[nb][amk][am0 + j * (NTHR / BK)] = rA[j];
#pragma unroll
            for (int j = 0; j < BLD; j++) Bs[nb][bk0 + j * (NTHR / BN)][bn] = rB[j];
            __syncthreads();
        }
    }
#pragma unroll
    for (int i = 0; i < TM; i++) {
        int m = m_off + ty * TM + i;
#pragma unroll
        for (int j = 0; j < TN; j++) {
            int n = n_off + tx * TN + j;
            float v = acc[i][j];
            if (bias) v += bias[n];
            C[(long)m * ldc + n] = v;
        }
    }
}

// ---------------- upfront: embed part of post logits (R7 verbatim) ------
__global__ void __launch_bounds__(256, 2)
k_embpart(const float* __restrict__ E, const float* __restrict__ Woo) {
    __shared__ __align__(16) float As[2][8][128 + 4];
    __shared__ __align__(16) float Bs[2][8][128];
    const int tid = threadIdx.x;
    const int N0 = blockIdx.x * 128, M0 = blockIdx.y * 128;
    const int am = tid >> 1, aq = tid & 1;
    const int bk = tid >> 5, bn4 = tid & 31;
    const int tx = tid % 16, ty = tid / 16;

    float4 ra, rb;
    float acc[8][8];
#pragma unroll
    for (int i = 0; i < 8; i++)
#pragma unroll
        for (int j = 0; j < 8; j++) acc[i][j] = 0.f;

    const float* Ap = E + (long)(M0 + am) * EE + aq * 4;
    const float* Bp = Woo + (long)(DD + bk) * SDIM + N0 + bn4 * 4;

    ra = *reinterpret_cast<const float4*>(Ap);
    rb = *reinterpret_cast<const float4*>(Bp);
    As[0][aq * 4 + 0][am] = ra.x; As[0][aq * 4 + 1][am] = ra.y;
    As[0][aq * 4 + 2][am] = ra.z; As[0][aq * 4 + 3][am] = ra.w;
    *reinterpret_cast<float4*>(&Bs[0][bk][bn4 * 4]) = rb;
    __syncthreads();

    for (int kt = 0; kt < 128; kt++) {
        int cur = kt & 1;
        if (kt + 1 < 128) {
            int kb = (kt + 1) * 8;
            ra = *reinterpret_cast<const float4*>(Ap + kb);
            rb = *reinterpret_cast<const float4*>(Bp + (long)kb * SDIM);
        }
#pragma unroll
        for (int kk = 0; kk < 8; kk++) {
            float4 a0 = *reinterpret_cast<const float4*>(&As[cur][kk][ty * 8]);
            float4 a1 = *reinterpret_cast<const float4*>(&As[cur][kk][ty * 8 + 4]);
            float4 b0 = *reinterpret_cast<const float4*>(&Bs[cur][kk][tx * 8]);
            float4 b1 = *reinterpret_cast<const float4*>(&Bs[cur][kk][tx * 8 + 4]);
            float a[8] = {a0.x, a0.y, a0.z, a0.w, a1.x, a1.y, a1.z, a1.w};
            float b[8] = {b0.x, b0.y, b0.z, b0.w, b1.x, b1.y, b1.z, b1.w};
#pragma unroll
            for (int i = 0; i < 8; i++)
#pragma unroll
                for (int j = 0; j < 8; j++) acc[i][j] += a[i] * b[j];
        }
        if (kt + 1 < 128) {
            int nb = cur ^ 1;
            As[nb][aq * 4 + 0][am] = ra.x; As[nb][aq * 4 + 1][am] = ra.y;
            As[nb][aq * 4 + 2][am] = ra.z; As[nb][aq * 4 + 3][am] = ra.w;
            *reinterpret_cast<float4*>(&Bs[nb][bk][bn4 * 4]) = rb;
            __syncthreads();
        }
    }
#pragma unroll
    for (int i = 0; i < 8; i++) {
        long row = (long)(M0 + ty * 8 + i) * SDIM + N0 + tx * 8;
        *reinterpret_cast<float4*>(&g_epart[row])     = make_float4(acc[i][0], acc[i][1], acc[i][2], acc[i][3]);
        *reinterpret_cast<float4*>(&g_epart[row + 4]) = make_float4(acc[i][4], acc[i][5], acc[i][6], acc[i][7]);
    }
}

// ---------------- init + x(0) --------------------------------------------
__global__ void k_init() {
    int i = blockIdx.x * blockDim.x + threadIdx.x;
    g_deter[i] = 0.f;
    if (i == 0) g_c1 = 0u;
}
__global__ void k_x0(const float* __restrict__ action, const float* __restrict__ W1,
                     const float* __restrict__ b1) {
    int b = blockIdx.x, col = threadIdx.x;
    float c3 = 0.f;
#pragma unroll
    for (int a = 0; a < AA; a++)
        c3 = fmaf(action[(long)b * TT * AA + a], W1[(SDIM + a) * HH + col], c3);
    g_x[b * HH + col] = b1[col] + c3;
}

// ---------------- JAX threefry2x32 gumbel (partitionable), fp32 logs ----
__device__ __forceinline__ uint32_t rotl32(uint32_t v, int r) {
    return (v << r) | (v >> (32 - r));
}
__device__ __forceinline__ float bits_to_gumbel(uint32_t b) {
    float u = __uint_as_float((b >> 9) | 0x3f800000u) - 1.0f;
    const float tinyv = 1.17549435e-38f;
    u = fmaxf(u, tinyv);
    float inner = -__nv_logf(u);
    return -__nv_logf(inner);
}
__global__ void k_gumbel() {
    unsigned i = blockIdx.x * blockDim.x + threadIdx.x;
    if (i >= (unsigned)NGUM) return;
    uint32_t x0 = 0u, x1 = i;
    const uint32_t ks0 = 0u, ks1 = 42u, ks2 = 0x1BD11BDAu ^ 0u ^ 42u;
    x0 += ks0; x1 += ks1;
#define TF_R4(a, b, c, d)                                   \
    x0 += x1; x1 = rotl32(x1, a); x1 ^= x0;                 \
    x0 += x1; x1 = rotl32(x1, b); x1 ^= x0;                 \
    x0 += x1; x1 = rotl32(x1, c); x1 ^= x0;                 \
    x0 += x1; x1 = rotl32(x1, d); x1 ^= x0;
    TF_R4(13, 15, 26, 6);  x0 += ks1; x1 += ks2 + 1u;
    TF_R4(17, 29, 16, 24); x0 += ks2; x1 += ks0 + 2u;
    TF_R4(13, 15, 26, 6);  x0 += ks0; x1 += ks1 + 3u;
    TF_R4(17, 29, 16, 24); x0 += ks1; x1 += ks2 + 4u;
    TF_R4(13, 15, 26, 6);  x0 += ks2; x1 += ks0 + 5u;
#undef TF_R4
    g_gumbel[i] = bits_to_gumbel(x0 ^ x1);
}

// ---------------- fused gates GEMMs + barrier + GRU ----------------------
// 96 blocks (<148 SMs -> all wave-1 resident; barrier cost = skew only).
// GEMM math identical to R7 k_gates; GRU math identical to R16 k_gru.
struct GiL {
    __device__ float operator()(int m, int k) const { return g_x[m * HH + k]; }
};
struct GhL {
    const float* isf; int t;
    __device__ float operator()(int m, int k) const {
        return g_deter[m * DD + k] * (1.0f - isf[m * TT + t]);
    }
};
__device__ __forceinline__ float sigm_f(float x) {
    return 1.0f / (1.0f + __nv_expf(-x));
}

__global__ void __launch_bounds__(256)
k_gatesgru(const float* __restrict__ Wih, const float* __restrict__ bih,
           const float* __restrict__ Whh, const float* __restrict__ bhh,
           const float* __restrict__ isf, float* __restrict__ out, int t) {
    const int bid = blockIdx.x;           // 0..95
    const int tid = threadIdx.x;

    // Phase 1: gates GEMM tiles (48 gi | 48 gh), R7 64x64 tiles.
    {
        int bz = bid / 48, rem = bid % 48, by = rem / 12, bx = rem % 12;
        if (bz == 0)
            gemm_db<64, 64, 16, 256>(GiL{}, Wih, 768, by * 64, bx * 64, 0, DD,
                                     g_gi, 768, bih);
        else
            gemm_db<64, 64, 16, 256>(GhL{isf, t}, Whh, 768, by * 64, bx * 64, 0, DD,
                                     g_gh, 768, bhh);
    }

    // Barrier: monotonic counter; all 96 blocks are resident (96 < 148).
    __syncthreads();
    if (tid == 0) {
        __threadfence();
        atomicAdd(&g_c1, 1u);
        volatile unsigned* p = &g_c1;
        unsigned tgt = (unsigned)(t + 1) * 96u;
        while (*p < tgt) __nanosleep(32);
    }
    __syncthreads();

    // Phase 2: GRU elementwise (cross-block reads via __ldcg).
    for (int base = bid * 256; base < BB * DD; base += 96 * 256) {
        int i = base + tid;
        if (i < BB * DD) {
            int b = i >> 8, d = i & 255;
            float ir = __ldcg(&g_gi[b * 768 + d]);
            float iz = __ldcg(&g_gi[b * 768 + 256 + d]);
            float in_ = __ldcg(&g_gi[b * 768 + 512 + d]);
            float hr = __ldcg(&g_gh[b * 768 + d]);
            float hz = __ldcg(&g_gh[b * 768 + 256 + d]);
            float hn = __ldcg(&g_gh[b * 768 + 512 + d]);
            float r = sigm_f(ir + hr);
            float z = sigm_f(iz + hz);
            float n = __nv_tanhf(in_ + r * hn);
            float h = g_deter[i] * (1.0f - isf[b * TT + t]);
            float nd = (1.0f - z) * n + z * h;
            g_deter[i] = nd;
            out[((long)b * TT + t) * OUTW + 2048 + d] = nd;
        }
    }
}

// ---------------- out GEMMs (R7 verbatim) --------------------------------
struct DetL {
    __device__ float operator()(int m, int k) const { return g_deter[m * DD + k]; }
};
__global__ void __launch_bounds__(256)
k_out(const float* __restrict__ Wio, const float* __restrict__ bio,
      const float* __restrict__ Woo, float* __restrict__ out, int t) {
    if (blockIdx.z == 0)
        gemm_db<64, 64, 16, 256>(DetL{}, Wio, SDIM,
                                 blockIdx.y * 64, blockIdx.x * 64, 0, DD,
                                 out + (long)t * OUTW + 2304, (long)TT * OUTW, bio);
    else
        gemm_db<64, 64, 16, 256>(DetL{}, Woo, SDIM,
                                 blockIdx.y * 64, blockIdx.x * 64, 0, DD,
                                 g_dpart, SDIM, nullptr);
}

// ---------------- sampling + x feedback (R7 verbatim) --------------------
__global__ void k_sample(const float* __restrict__ isf, const float* __restrict__ action,
                         const float* __restrict__ W1, const float* __restrict__ b1,
                         const float* __restrict__ boo, float* __restrict__ out, int t) {
    int b = blockIdx.x;
    int draw = blockIdx.y;
    int tid = threadIdx.x, lane = tid & 31, w = tid >> 5;
    __shared__ int sidx[SS];
    long obase = ((long)b * TT + t) * OUTW;

#pragma unroll
    for (int q = 0; q < 4; q++) {
        int g = w * 4 + q;
        int col = g * 32 + lane;
        float lv;
        if (draw == 0) {
            lv = out[obase + 2304 + col];
        } else {
            lv = (g_dpart[b * SDIM + col] + g_epart[((long)b * TT + t) * SDIM + col]) + boo[col];
            out[obase + col] = lv;
        }
        float gum = g_gumbel[(((long)draw * TT + t) * BB + b) * SDIM + col];
        float v = lv + gum;
        int idx = lane;
#pragma unroll
        for (int off = 16; off > 0; off >>= 1) {
            float v2 = __shfl_xor_sync(0xffffffffu, v, off);
            int i2 = __shfl_xor_sync(0xffffffffu, idx, off);
            if (v2 > v || (v2 == v && i2 < idx)) { v = v2; idx = i2; }
        }
        float oh = (lane == idx) ? 1.0f : 0.0f;
        out[obase + (draw ? 1024 : 3328) + col] = oh;
        if (draw && lane == 0) sidx[g] = idx;
    }

    if (draw == 1 && t + 1 < TT) {
        __syncthreads();
        int col = tid;
        float mask = 1.0f - isf[b * TT + (t + 1)];
        float c0 = 0.f, c1 = 0.f, c2 = 0.f, c3 = 0.f;
        int i8 = sidx[8], i25 = sidx[25];
#pragma unroll
        for (int s2 = 0; s2 < 8; s2++)
            c0 = fmaf(mask, W1[(s2 * 32 + sidx[s2]) * HH + col], c0);
        {
            float wv = W1[(8 * 32 + i8) * HH + col];
            if (i8 < 16) c0 = fmaf(mask, wv, c0); else c1 = fmaf(mask, wv, c1);
        }
#pragma unroll
        for (int s2 = 9; s2 < 17; s2++)
            c1 = fmaf(mask, W1[(s2 * 32 + sidx[s2]) * HH + col], c1);
#pragma unroll
        for (int s2 = 17; s2 < 25; s2++)
            c2 = fmaf(mask, W1[(s2 * 32 + sidx[s2]) * HH + col], c2);
        {
            float wv = W1[(25 * 32 + i25) * HH + col];
            if (i25 < 16) c2 = fmaf(mask, wv, c2); else c3 = fmaf(mask, wv, c3);
        }
#pragma unroll
        for (int s2 = 26; s2 < 32; s2++)
            c3 = fmaf(mask, W1[(s2 * 32 + sidx[s2]) * HH + col], c3);
#pragma unroll
        for (int a = 0; a < AA; a++)
            c3 = fmaf(action[((long)b * TT + (t + 1)) * AA + a],
                      W1[(SDIM + a) * HH + col], c3);
        g_x[b * HH + col] = (((c0 + b1[col]) + c1) + c2) + c3;
    }
}

// ---------------- launch ----------------
extern "C" void kernel_launch(void* const* d_in, const int* in_sizes, int n_in,
                              void* d_out, int out_size) {
    (void)in_sizes; (void)n_in; (void)out_size;
    const float* embed     = (const float*)d_in[0];
    const float* action    = (const float*)d_in[1];
    const float* isf       = (const float*)d_in[2];
    const float* W_img_in  = (const float*)d_in[3];
    const float* b_img_in  = (const float*)d_in[4];
    const float* W_ih      = (const float*)d_in[5];
    const float* b_ih      = (const float*)d_in[6];
    const float* W_hh      = (const float*)d_in[7];
    const float* b_hh      = (const float*)d_in[8];
    const float* W_img_out = (const float*)d_in[9];
    const float* b_img_out = (const float*)d_in[10];
    const float* W_obs_out = (const float*)d_in[11];
    const float* b_obs_out = (const float*)d_in[12];
    float* out = (float*)d_out;

    k_embpart<<<dim3(8, 128), 256>>>(embed, W_obs_out);
    k_gumbel<<<NGUM / 256, 256>>>();
    k_init<<<256, 256>>>();
    k_x0<<<256, 256>>>(action, W_img_in, b_img_in);
    for (int t = 0; t < TT; t++) {
        k_gatesgru<<<96, 256>>>(W_ih, b_ih, W_hh, b_hh, isf, out, t);
        k_out<<<dim3(16, 4, 2), 256>>>(W_img_out, b_img_out, W_obs_out, out, t);
        k_sample<<<dim3(256, 2), 256>>>(isf, action, W_img_in, b_img_in,
                                        b_obs_out, out, t);
    }
}